// round 11
// baseline (speedup 1.0000x reference)
#include <cuda_runtime.h>
#include <cuda_bf16.h>
#include <math.h>

#define S_LEN  512
#define BATCH  4
#define NHEAD  16
#define BH     (BATCH * NHEAD)
#define DHEAD  64
#define DMODEL 1024
#define D3     3072
#define NTOK   2048   // BATCH * S_LEN

typedef unsigned long long u64;

// ---------------- bf16 mma helper (m16n8k16, verified layout) ----------------
__device__ __forceinline__ void mma_bf16(float* c, const unsigned* a, const unsigned* b) {
    asm volatile("mma.sync.aligned.m16n8k16.row.col.f32.bf16.bf16.f32 "
        "{%0,%1,%2,%3}, {%4,%5,%6,%7}, {%8,%9}, {%0,%1,%2,%3};"
        : "+f"(c[0]), "+f"(c[1]), "+f"(c[2]), "+f"(c[3])
        : "r"(a[0]), "r"(a[1]), "r"(a[2]), "r"(a[3]), "r"(b[0]), "r"(b[1]));
}

// split fp32 pair (a,b) into packed bf16 hi word + bf16 lo (residual) word
__device__ __forceinline__ void split_pair(float a, float b, unsigned& H, unsigned& L) {
    __nv_bfloat162 h2 = __floats2bfloat162_rn(a, b);
    float ra = a - __bfloat162float(h2.x);
    float rb = b - __bfloat162float(h2.y);
    __nv_bfloat162 l2 = __floats2bfloat162_rn(ra, rb);
    H = *(unsigned*)&h2;
    L = *(unsigned*)&l2;
}

__device__ __forceinline__ void cp16(unsigned dst_smem, const void* src) {
    asm volatile("cp.async.cg.shared.global [%0], [%1], 16;"
                 :: "r"(dst_smem), "l"(src));
}

// ---------------- scratch (static device globals; no allocation) ----------------
__device__ float g_qkv_r[NTOK * D3];       // 25.2 MB
__device__ float g_qkv_i[NTOK * D3];
__device__ float g_rc[S_LEN * DHEAD];
__device__ float g_rs[S_LEN * DHEAD];
// pre-split operands: packed bf16 H/L pair-words, row-major [row][K/2 words]
__device__ unsigned g_xRH[NTOK * 512],  g_xRL[NTOK * 512];
__device__ unsigned g_xIH[NTOK * 512],  g_xIL[NTOK * 512];
__device__ unsigned g_wqRH[D3 * 512],   g_wqRL[D3 * 512];
__device__ unsigned g_wqIH[D3 * 512],   g_wqIL[D3 * 512];
__device__ unsigned g_woRH[DMODEL * 512], g_woRL[DMODEL * 512];
__device__ unsigned g_woIH[DMODEL * 512], g_woIL[DMODEL * 512];
__device__ unsigned g_aoRH[NTOK * 512], g_aoRL[NTOK * 512];   // attn out (pre-split)
__device__ unsigned g_aoIH[NTOK * 512], g_aoIL[NTOK * 512];
// rotated K, bf16 H/L packed pairs, layout [bh][s][d-pair word] (B-frag ready)
__device__ unsigned g_kbrH[BH * 512 * 32], g_kbrL[BH * 512 * 32];
__device__ unsigned g_kbiH[BH * 512 * 32], g_kbiL[BH * 512 * 32];
// V transposed, bf16 H/L packed pairs, layout [bh][d][s-pair word] (B-frag ready)
__device__ unsigned g_vtrH[BH * 64 * 256], g_vtrL[BH * 64 * 256];
__device__ unsigned g_vtiH[BH * 64 * 256], g_vtiL[BH * 64 * 256];

// ---------------- RoPE rotor table ----------------
__global__ void rope_table_kernel() {
    int s = blockIdx.x, d = threadIdx.x;
    float inv = powf(10000.0f, -((float)d) / 64.0f);
    float ang = (float)s * inv;
    g_rc[s * DHEAD + d] = cosf(ang);
    g_rs[s * DHEAD + d] = sinf(ang);
}

// ---------------- generic fp32 -> bf16 H/L pack ----------------
__global__ __launch_bounds__(256)
void pack_kernel(const float* __restrict__ src,
                 unsigned* __restrict__ H, unsigned* __restrict__ L)
{
    int i = blockIdx.x * 256 + threadIdx.x;
    float2 v = ((const float2*)src)[i];
    split_pair(v.x, v.y, H[i], L[i]);
}

// ======= pipelined complex GEMM, pre-split bf16 H/L inputs: C = A * B^T =======
// tile 128(M) x 64(N) x 16(K), 256 threads (8 warps, 4x2), cp.async 2-stage.
// smem stage (words): aRH 0, aRL 1536, aIH 3072, aIL 4608,
//                     bRH 6144, bRL 6912, bIH 7680, bIL 8448;  stage = 9216 words
#define CG_STG   9216
#define CG_SMEM  (2 * CG_STG * 4)
__global__ __launch_bounds__(256)
void cgemm_pk_kernel(const unsigned* __restrict__ aRH, const unsigned* __restrict__ aRL,
                     const unsigned* __restrict__ aIH, const unsigned* __restrict__ aIL,
                     const unsigned* __restrict__ bRH, const unsigned* __restrict__ bRL,
                     const unsigned* __restrict__ bIH, const unsigned* __restrict__ bIL,
                     float* __restrict__ Cr, float* __restrict__ Ci,
                     int N, int Kw /* K/2 words per row */)
{
    extern __shared__ unsigned sm[];
    int tid = threadIdx.x;
    int lane = tid & 31, w = tid >> 5;
    int wm = (w & 3) * 32;      // warp m-offset (0,32,64,96)
    int wn = (w >> 2) * 32;     // warp n-offset (0,32)
    int g = lane >> 2, t = lane & 3;
    int m0 = blockIdx.y * 128;
    int n0 = blockIdx.x * 64;
    int NK = Kw / 8;            // k-tiles of 8 words (16 elems)

    // loader mapping (each thread: 4 A-chunks + 2 B-chunks of 16B per stage)
    int rA = tid >> 1, hA = tid & 1;
    size_t srcA = (size_t)(m0 + rA) * Kw + hA * 4;
    int dstA = rA * 12 + hA * 4;
    int rB = (tid & 127) >> 1;
    int aB = tid >> 7;          // 0 or 1
    size_t srcB = (size_t)(n0 + rB) * Kw + hA * 4;
    int dstB1 = 6144 + aB * 768 + rB * 12 + hA * 4;
    int dstB2 = dstB1 + 2 * 768;
    const unsigned* pB1 = aB ? bRL : bRH;
    const unsigned* pB2 = aB ? bIL : bIH;

    unsigned smB = (unsigned)__cvta_generic_to_shared(sm);

    auto issue = [&](int stage, int kt) {
        unsigned sb = smB + stage * (CG_STG * 4);
        size_t ko = (size_t)kt * 8;
        cp16(sb + (0 * 1536 + dstA) * 4, aRH + srcA + ko);
        cp16(sb + (1 * 1536 + dstA) * 4, aRL + srcA + ko);
        cp16(sb + (2 * 1536 + dstA) * 4, aIH + srcA + ko);
        cp16(sb + (3 * 1536 + dstA) * 4, aIL + srcA + ko);
        cp16(sb + dstB1 * 4, pB1 + srcB + ko);
        cp16(sb + dstB2 * 4, pB2 + srcB + ko);
        asm volatile("cp.async.commit_group;");
    };

    float accR[8][4], accI[8][4];
#pragma unroll
    for (int p = 0; p < 8; p++)
#pragma unroll
        for (int j = 0; j < 4; j++) { accR[p][j] = 0.f; accI[p][j] = 0.f; }

    issue(0, 0);
    issue(1, 1);

    for (int kt = 0; kt < NK; kt++) {
        int buf = kt & 1;
        asm volatile("cp.async.wait_group 1;");
        __syncthreads();
        unsigned* st = sm + buf * CG_STG;

        // A fragments (stride 12, verified conflict-free)
        unsigned fRH[2][4], fRL[2][4], fIH[2][4], fIL[2][4];
#pragma unroll
        for (int mt = 0; mt < 2; mt++) {
            int r0 = (wm + mt * 16 + g) * 12 + t;
            int r1 = r0 + 8 * 12;
            fRH[mt][0] = st[r0];            fRH[mt][1] = st[r1];
            fRH[mt][2] = st[r0 + 4];        fRH[mt][3] = st[r1 + 4];
            fRL[mt][0] = st[1536 + r0];     fRL[mt][1] = st[1536 + r1];
            fRL[mt][2] = st[1536 + r0 + 4]; fRL[mt][3] = st[1536 + r1 + 4];
            fIH[mt][0] = st[3072 + r0];     fIH[mt][1] = st[3072 + r1];
            fIH[mt][2] = st[3072 + r0 + 4]; fIH[mt][3] = st[3072 + r1 + 4];
            fIL[mt][0] = st[4608 + r0];     fIL[mt][1] = st[4608 + r1];
            fIL[mt][2] = st[4608 + r0 + 4]; fIL[mt][3] = st[4608 + r1 + 4];
        }

#pragma unroll
        for (int nt = 0; nt < 4; nt++) {
            int rb = 6144 + (wn + nt * 8 + g) * 12 + t;
            unsigned brH[2] = {st[rb],        st[rb + 4]};
            unsigned brL[2] = {st[rb + 768],  st[rb + 768 + 4]};
            unsigned biH[2] = {st[rb + 1536], st[rb + 1536 + 4]};
            unsigned biL[2] = {st[rb + 2304], st[rb + 2304 + 4]};
            unsigned nbiH[2] = {biH[0] ^ 0x80008000u, biH[1] ^ 0x80008000u};
            unsigned nbiL[2] = {biL[0] ^ 0x80008000u, biL[1] ^ 0x80008000u};
#pragma unroll
            for (int mt = 0; mt < 2; mt++) {
                int p = mt * 4 + nt;
                // re = Ar*Br - Ai*Bi   (3-term compensated each)
                mma_bf16(accR[p], fRH[mt], brH);
                mma_bf16(accR[p], fRH[mt], brL);
                mma_bf16(accR[p], fRL[mt], brH);
                mma_bf16(accR[p], fIH[mt], nbiH);
                mma_bf16(accR[p], fIH[mt], nbiL);
                mma_bf16(accR[p], fIL[mt], nbiH);
                // im = Ar*Bi + Ai*Br
                mma_bf16(accI[p], fRH[mt], biH);
                mma_bf16(accI[p], fRH[mt], biL);
                mma_bf16(accI[p], fRL[mt], biH);
                mma_bf16(accI[p], fIH[mt], brH);
                mma_bf16(accI[p], fIH[mt], brL);
                mma_bf16(accI[p], fIL[mt], brH);
            }
        }

        __syncthreads();
        if (kt + 2 < NK) issue(buf, kt + 2);
        else asm volatile("cp.async.commit_group;");   // keep group count sound
    }

    // epilogue
#pragma unroll
    for (int mt = 0; mt < 2; mt++)
#pragma unroll
        for (int nt = 0; nt < 4; nt++) {
            int p = mt * 4 + nt;
            int m = m0 + wm + mt * 16 + g;
            int n = n0 + wn + nt * 8 + t * 2;
            size_t c0 = (size_t)m * N + n;
            size_t c1 = (size_t)(m + 8) * N + n;
            *(float2*)(Cr + c0) = make_float2(accR[p][0], accR[p][1]);
            *(float2*)(Cr + c1) = make_float2(accR[p][2], accR[p][3]);
            *(float2*)(Ci + c0) = make_float2(accI[p][0], accI[p][1]);
            *(float2*)(Ci + c1) = make_float2(accI[p][2], accI[p][3]);
        }
}

// ---------- K: rotate + split to bf16 H/L pairs, layout [bh][s][d-pair] ----------
__global__ __launch_bounds__(256)
void kpack_kernel(const float* __restrict__ qkv_r, const float* __restrict__ qkv_i)
{
    int bh = blockIdx.y;
    int b = bh >> 4, h = bh & 15;
    int id = blockIdx.x * 256 + threadIdx.x;   // 0..16383 = s*32 + wd
    int s = id >> 5, wd = id & 31;
    int d = 2 * wd;
    size_t off = ((size_t)b * S_LEN + s) * D3 + DMODEL + (size_t)h * DHEAD + d;
    float2 kr = *(const float2*)(qkv_r + off);
    float2 ki = *(const float2*)(qkv_i + off);
    float2 co = *(const float2*)(g_rc + s * DHEAD + d);
    float2 si = *(const float2*)(g_rs + s * DHEAD + d);
    float r0 = kr.x * co.x - ki.x * si.x;
    float i0 = kr.x * si.x + ki.x * co.x;
    float r1 = kr.y * co.y - ki.y * si.y;
    float i1 = kr.y * si.y + ki.y * co.y;
    size_t o = (size_t)bh * 16384 + id;
    unsigned H, L;
    split_pair(r0, r1, H, L); g_kbrH[o] = H; g_kbrL[o] = L;
    split_pair(i0, i1, H, L); g_kbiH[o] = H; g_kbiL[o] = L;
}

// ---------- V: transpose + split to bf16 H/L pairs, layout [bh][d][s-pair] ----------
__global__ __launch_bounds__(256)
void vpack_kernel(const float* __restrict__ qkv_r, const float* __restrict__ qkv_i)
{
    __shared__ float sVr[64][65], sVi[64][65];
    int sc = blockIdx.x;       // s-chunk of 64
    int bh = blockIdx.y;
    int b = bh >> 4, h = bh & 15;
    int tid = threadIdx.x;

#pragma unroll
    for (int i = 0; i < 16; i++) {
        int id = i * 256 + tid;        // 0..4095 = sl*64 + d
        int sl = id >> 6, d = id & 63;
        size_t off = ((size_t)b * S_LEN + sc * 64 + sl) * D3 + 2 * DMODEL
                   + (size_t)h * DHEAD + d;
        sVr[sl][d] = qkv_r[off];
        sVi[sl][d] = qkv_i[off];
    }
    __syncthreads();

#pragma unroll
    for (int i = 0; i < 8; i++) {
        int id = i * 256 + tid;        // 0..2047 = d*32 + ws
        int d = id >> 5, ws = id & 31;
        size_t o = ((size_t)bh * 64 + d) * 256 + sc * 32 + ws;
        unsigned H, L;
        split_pair(sVr[2 * ws][d], sVr[2 * ws + 1][d], H, L);
        g_vtrH[o] = H; g_vtrL[o] = L;
        split_pair(sVi[2 * ws][d], sVi[2 * ws + 1][d], H, L);
        g_vtiH[o] = H; g_vtiL[o] = L;
    }
}

// ========== fused attention, all-MMA: one block per (b, h, 16-q tile) ==========
#define OFF_QRH 0
#define OFF_QRL 576
#define OFF_QIH 1152
#define OFF_QIL 1728
#define OFF_WC  2304
#define OFF_WS  10528
#define OFF_WCH 18752
#define OFF_WCL 22912
#define OFF_WSH 27072
#define OFF_WSL 31232
#define ATTN_SMEM_WORDS 35392
#define ATTN_SMEM (ATTN_SMEM_WORDS * 4)

__global__ __launch_bounds__(256)
void attn_kernel(const float* __restrict__ qkv_r, const float* __restrict__ qkv_i)
{
    extern __shared__ unsigned sm[];
    unsigned* sQrH = sm + OFF_QRH;
    unsigned* sQrL = sm + OFF_QRL;
    unsigned* sQiH = sm + OFF_QIH;
    unsigned* sQiL = sm + OFF_QIL;
    float* sWc = (float*)(sm + OFF_WC);
    float* sWs = (float*)(sm + OFF_WS);
    unsigned* sWcH = sm + OFF_WCH;
    unsigned* sWcL = sm + OFF_WCL;
    unsigned* sWsH = sm + OFF_WSH;
    unsigned* sWsL = sm + OFF_WSL;

    int tid = threadIdx.x;
    int w = tid >> 5, l = tid & 31;
    int g = l >> 2, t = l & 3;
    int h = blockIdx.y, b = blockIdx.z;
    int bh = b * NHEAD + h;
    int q0 = blockIdx.x * 16;
    const size_t tok = (size_t)b * S_LEN;

    // ---- Q: load + rotate + split, word layout [q][d-pair] stride 36 ----
#pragma unroll
    for (int i = 0; i < 2; i++) {
        int id = tid + 256 * i;        // 0..511 = q*32 + wd
        int q = id >> 5, wd = id & 31;
        int s = q0 + q;
        int d = 2 * wd;
        size_t off = (tok + s) * D3 + (size_t)h * DHEAD + d;
        float2 qr = *(const float2*)(qkv_r + off);
        float2 qi = *(const float2*)(qkv_i + off);
        float2 co = *(const float2*)(g_rc + s * DHEAD + d);
        float2 si = *(const float2*)(g_rs + s * DHEAD + d);
        float r0 = qr.x * co.x - qi.x * si.x;
        float i0 = qr.x * si.x + qi.x * co.x;
        float r1 = qr.y * co.y - qi.y * si.y;
        float i1 = qr.y * si.y + qi.y * co.y;
        unsigned H, L;
        split_pair(r0, r1, H, L); sQrH[q * 36 + wd] = H; sQrL[q * 36 + wd] = L;
        split_pair(i0, i1, H, L); sQiH[q * 36 + wd] = H; sQiL[q * 36 + wd] = L;
    }
    __syncthreads();

    // ---- scores MMA: warp w owns k-rows [64w, 64w+64) ----
    {
        float accR[8][4], accI[8][4];
#pragma unroll
        for (int p = 0; p < 8; p++)
#pragma unroll
            for (int j = 0; j < 4; j++) { accR[p][j] = 0.f; accI[p][j] = 0.f; }

        const size_t kbase = (size_t)bh * 16384;
#pragma unroll
        for (int ks = 0; ks < 4; ks++) {
            int r0 = g * 36 + ks * 8 + t;
            int r1 = (g + 8) * 36 + ks * 8 + t;
            unsigned aQrH[4] = {sQrH[r0], sQrH[r1], sQrH[r0 + 4], sQrH[r1 + 4]};
            unsigned aQrL[4] = {sQrL[r0], sQrL[r1], sQrL[r0 + 4], sQrL[r1 + 4]};
            unsigned aQiH[4] = {sQiH[r0], sQiH[r1], sQiH[r0 + 4], sQiH[r1 + 4]};
            unsigned aQiL[4] = {sQiL[r0], sQiL[r1], sQiL[r0 + 4], sQiL[r1 + 4]};
            unsigned nQrH[4], nQrL[4];
#pragma unroll
            for (int j = 0; j < 4; j++) {
                nQrH[j] = aQrH[j] ^ 0x80008000u;
                nQrL[j] = aQrL[j] ^ 0x80008000u;
            }
#pragma unroll
            for (int nt = 0; nt < 8; nt++) {
                int srow = w * 64 + nt * 8 + g;
                size_t kb = kbase + (size_t)srow * 32 + ks * 8 + t;
                unsigned krH[2] = {g_kbrH[kb], g_kbrH[kb + 4]};
                unsigned krL[2] = {g_kbrL[kb], g_kbrL[kb + 4]};
                unsigned kiH[2] = {g_kbiH[kb], g_kbiH[kb + 4]};
                unsigned kiL[2] = {g_kbiL[kb], g_kbiL[kb + 4]};
                mma_bf16(accR[nt], aQrH, krH);
                mma_bf16(accR[nt], aQrH, krL);
                mma_bf16(accR[nt], aQrL, krH);
                mma_bf16(accR[nt], aQiH, kiH);
                mma_bf16(accR[nt], aQiH, kiL);
                mma_bf16(accR[nt], aQiL, kiH);
                mma_bf16(accI[nt], aQiH, krH);
                mma_bf16(accI[nt], aQiH, krL);
                mma_bf16(accI[nt], aQiL, krH);
                mma_bf16(accI[nt], nQrH, kiH);
                mma_bf16(accI[nt], nQrH, kiL);
                mma_bf16(accI[nt], nQrL, kiH);
            }
        }

        const float scale = 0.125f;   // 1/sqrt(64)
#pragma unroll
        for (int nt = 0; nt < 8; nt++) {
            int col = w * 64 + nt * 8 + 2 * t;
            *(float2*)&sWc[g * 514 + col] =
                make_float2(accR[nt][0] * scale, accR[nt][1] * scale);
            *(float2*)&sWc[(g + 8) * 514 + col] =
                make_float2(accR[nt][2] * scale, accR[nt][3] * scale);
            *(float2*)&sWs[g * 514 + col] =
                make_float2(accI[nt][0] * scale, accI[nt][1] * scale);
            *(float2*)&sWs[(g + 8) * 514 + col] =
                make_float2(accI[nt][2] * scale, accI[nt][3] * scale);
        }
    }
    __syncthreads();

    // ---- softmax + complex weights (bf16 H/L split): warp w -> rows w, w+8 ----
#pragma unroll
    for (int rr = 0; rr < 2; rr++) {
        int row = w + rr * 8;
        float* rc_ = sWc + row * 514;
        float* rs_ = sWs + row * 514;

        float mx = -1e30f;
#pragma unroll
        for (int j = 0; j < 16; j++) mx = fmaxf(mx, rc_[l + 32 * j]);
#pragma unroll
        for (int o = 16; o > 0; o >>= 1)
            mx = fmaxf(mx, __shfl_xor_sync(0xffffffff, mx, o));

        float sum = 0.f;
#pragma unroll
        for (int j = 0; j < 16; j++) {
            int idx = l + 32 * j;
            float e = __expf(rc_[idx] - mx);
            rc_[idx] = e;
            sum += e;
        }
#pragma unroll
        for (int o = 16; o > 0; o >>= 1)
            sum += __shfl_xor_sync(0xffffffff, sum, o);
        float inv = 1.0f / sum;

#pragma unroll
        for (int j = 0; j < 8; j++) {
            int k0 = 2 * l + 64 * j;
            int wd = l + 32 * j;
            float p0 = rc_[k0] * inv, p1 = rc_[k0 + 1] * inv;
            float s0, c0, s1, c1;
            sincosf(rs_[k0], &s0, &c0);
            sincosf(rs_[k0 + 1], &s1, &c1);
            unsigned H, L;
            split_pair(p0 * c0, p1 * c1, H, L);
            sWcH[row * 260 + wd] = H; sWcL[row * 260 + wd] = L;
            split_pair(p0 * s0, p1 * s1, H, L);
            sWsH[row * 260 + wd] = H; sWsL[row * 260 + wd] = L;
        }
    }
    __syncthreads();

    // ---- AV MMA: warp w -> d-cols [8w, 8w+8); epilogue writes pre-split H/L ----
    {
        float oR[4] = {0.f, 0.f, 0.f, 0.f};
        float oI[4] = {0.f, 0.f, 0.f, 0.f};
        const size_t vbase = ((size_t)bh * 64 + 8 * w + g) * 256;
#pragma unroll 4
        for (int ks = 0; ks < 32; ks++) {
            int r0 = g * 260 + ks * 8 + t;
            int r1 = (g + 8) * 260 + ks * 8 + t;
            unsigned awcH[4] = {sWcH[r0], sWcH[r1], sWcH[r0 + 4], sWcH[r1 + 4]};
            unsigned awcL[4] = {sWcL[r0], sWcL[r1], sWcL[r0 + 4], sWcL[r1 + 4]};
            unsigned awsH[4] = {sWsH[r0], sWsH[r1], sWsH[r0 + 4], sWsH[r1 + 4]};
            unsigned awsL[4] = {sWsL[r0], sWsL[r1], sWsL[r0 + 4], sWsL[r1 + 4]};
            unsigned nwsH[4], nwsL[4];
#pragma unroll
            for (int j = 0; j < 4; j++) {
                nwsH[j] = awsH[j] ^ 0x80008000u;
                nwsL[j] = awsL[j] ^ 0x80008000u;
            }
            size_t vb = vbase + ks * 8 + t;
            unsigned vrH[2] = {g_vtrH[vb], g_vtrH[vb + 4]};
            unsigned vrL[2] = {g_vtrL[vb], g_vtrL[vb + 4]};
            unsigned viH[2] = {g_vtiH[vb], g_vtiH[vb + 4]};
            unsigned viL[2] = {g_vtiL[vb], g_vtiL[vb + 4]};
            mma_bf16(oR, awcH, vrH);
            mma_bf16(oR, awcH, vrL);
            mma_bf16(oR, awcL, vrH);
            mma_bf16(oR, nwsH, viH);
            mma_bf16(oR, nwsH, viL);
            mma_bf16(oR, nwsL, viH);
            mma_bf16(oI, awcH, viH);
            mma_bf16(oI, awcH, viL);
            mma_bf16(oI, awcL, viH);
            mma_bf16(oI, awsH, vrH);
            mma_bf16(oI, awsH, vrL);
            mma_bf16(oI, awsL, vrH);
        }
        int wcol = h * 32 + 4 * w + t;          // word col in [tok][512] layout
        size_t r0w = (tok + q0 + g) * 512 + wcol;
        size_t r1w = (tok + q0 + g + 8) * 512 + wcol;
        unsigned H, L;
        split_pair(oR[0], oR[1], H, L); g_aoRH[r0w] = H; g_aoRL[r0w] = L;
        split_pair(oR[2], oR[3], H, L); g_aoRH[r1w] = H; g_aoRL[r1w] = L;
        split_pair(oI[0], oI[1], H, L); g_aoIH[r0w] = H; g_aoIL[r0w] = L;
        split_pair(oI[2], oI[3], H, L); g_aoIH[r1w] = H; g_aoIL[r1w] = L;
    }
}

// ---------------- launch ----------------
extern "C" void kernel_launch(void* const* d_in, const int* in_sizes, int n_in,
                              void* d_out, int out_size)
{
    const float* x_re    = (const float*)d_in[0];
    const float* x_im    = (const float*)d_in[1];
    const float* wqkv_re = (const float*)d_in[2];
    const float* wqkv_im = (const float*)d_in[3];
    const float* wo_re   = (const float*)d_in[4];
    const float* wo_im   = (const float*)d_in[5];
    float* out = (float*)d_out;

    float *qkv_r, *qkv_i;
    cudaGetSymbolAddress((void**)&qkv_r, g_qkv_r);
    cudaGetSymbolAddress((void**)&qkv_i, g_qkv_i);
    unsigned *xRH, *xRL, *xIH, *xIL, *wqRH, *wqRL, *wqIH, *wqIL;
    unsigned *woRH, *woRL, *woIH, *woIL, *aoRH, *aoRL, *aoIH, *aoIL;
    cudaGetSymbolAddress((void**)&xRH, g_xRH);   cudaGetSymbolAddress((void**)&xRL, g_xRL);
    cudaGetSymbolAddress((void**)&xIH, g_xIH);   cudaGetSymbolAddress((void**)&xIL, g_xIL);
    cudaGetSymbolAddress((void**)&wqRH, g_wqRH); cudaGetSymbolAddress((void**)&wqRL, g_wqRL);
    cudaGetSymbolAddress((void**)&wqIH, g_wqIH); cudaGetSymbolAddress((void**)&wqIL, g_wqIL);
    cudaGetSymbolAddress((void**)&woRH, g_woRH); cudaGetSymbolAddress((void**)&woRL, g_woRL);
    cudaGetSymbolAddress((void**)&woIH, g_woIH); cudaGetSymbolAddress((void**)&woIL, g_woIL);
    cudaGetSymbolAddress((void**)&aoRH, g_aoRH); cudaGetSymbolAddress((void**)&aoRL, g_aoRL);
    cudaGetSymbolAddress((void**)&aoIH, g_aoIH); cudaGetSymbolAddress((void**)&aoIL, g_aoIL);

    cudaFuncSetAttribute(attn_kernel,
                         cudaFuncAttributeMaxDynamicSharedMemorySize, ATTN_SMEM);
    cudaFuncSetAttribute(cgemm_pk_kernel,
                         cudaFuncAttributeMaxDynamicSharedMemorySize, CG_SMEM);

    // 1. RoPE rotor table + operand pre-splits
    rope_table_kernel<<<S_LEN, DHEAD>>>();
    pack_kernel<<<NTOK * 512 / 256, 256>>>(x_re, xRH, xRL);
    pack_kernel<<<NTOK * 512 / 256, 256>>>(x_im, xIH, xIL);
    pack_kernel<<<D3 * 512 / 256, 256>>>(wqkv_re, wqRH, wqRL);
    pack_kernel<<<D3 * 512 / 256, 256>>>(wqkv_im, wqIH, wqIL);
    pack_kernel<<<DMODEL * 512 / 256, 256>>>(wo_re, woRH, woRL);
    pack_kernel<<<DMODEL * 512 / 256, 256>>>(wo_im, woIH, woIL);

    // 2. complex QKV projection (pipelined, pre-split bf16x3)
    dim3 g1(D3 / 64, NTOK / 128);
    cgemm_pk_kernel<<<g1, 256, CG_SMEM>>>(xRH, xRL, xIH, xIL,
                                          wqRH, wqRL, wqIH, wqIL,
                                          qkv_r, qkv_i, D3, DMODEL / 2);

    // 3. K rotate+split and V transpose+split into MMA-ready bf16 H/L arrays
    dim3 g2(64, BH);
    kpack_kernel<<<g2, 256>>>(qkv_r, qkv_i);
    dim3 g3(S_LEN / 64, BH);
    vpack_kernel<<<g3, 256>>>(qkv_r, qkv_i);

    // 4. fused all-MMA attention, 16 q-rows per block (writes pre-split output)
    dim3 g4(S_LEN / 16, NHEAD, BATCH);
    attn_kernel<<<g4, 256, ATTN_SMEM>>>(qkv_r, qkv_i);

    // 5. complex output projection straight into d_out ([2,B,S,D])
    dim3 g5(DMODEL / 64, NTOK / 128);
    cgemm_pk_kernel<<<g5, 256, CG_SMEM>>>(aoRH, aoRL, aoIH, aoIL,
                                          woRH, woRL, woIH, woIL,
                                          out, out + (size_t)NTOK * DMODEL,
                                          DMODEL, DMODEL / 2);
}

// round 13
// speedup vs baseline: 1.0885x; 1.0885x over previous
#include <cuda_runtime.h>
#include <cuda_bf16.h>
#include <math.h>

#define S_LEN  512
#define BATCH  4
#define NHEAD  16
#define BH     (BATCH * NHEAD)
#define DHEAD  64
#define DMODEL 1024
#define D3     3072
#define NTOK   2048   // BATCH * S_LEN

typedef unsigned long long u64;

// ---------------- bf16 mma helper (m16n8k16, verified layout) ----------------
__device__ __forceinline__ void mma_bf16(float* c, const unsigned* a, const unsigned* b) {
    asm volatile("mma.sync.aligned.m16n8k16.row.col.f32.bf16.bf16.f32 "
        "{%0,%1,%2,%3}, {%4,%5,%6,%7}, {%8,%9}, {%0,%1,%2,%3};"
        : "+f"(c[0]), "+f"(c[1]), "+f"(c[2]), "+f"(c[3])
        : "r"(a[0]), "r"(a[1]), "r"(a[2]), "r"(a[3]), "r"(b[0]), "r"(b[1]));
}

// split fp32 pair (a,b) into packed bf16 hi word + bf16 lo (residual) word
__device__ __forceinline__ void split_pair(float a, float b, unsigned& H, unsigned& L) {
    __nv_bfloat162 h2 = __floats2bfloat162_rn(a, b);
    float ra = a - __bfloat162float(h2.x);
    float rb = b - __bfloat162float(h2.y);
    __nv_bfloat162 l2 = __floats2bfloat162_rn(ra, rb);
    H = *(unsigned*)&h2;
    L = *(unsigned*)&l2;
}

// ---------------- scratch (static device globals; no allocation) ----------------
__device__ float g_qkv_r[NTOK * D3];       // 25.2 MB
__device__ float g_qkv_i[NTOK * D3];
__device__ float g_rc[S_LEN * DHEAD];
__device__ float g_rs[S_LEN * DHEAD];
// pre-split operands: packed bf16 H/L pair-words, row-major [row][K/2 words]
__device__ unsigned g_xRH[NTOK * 512],  g_xRL[NTOK * 512];
__device__ unsigned g_xIH[NTOK * 512],  g_xIL[NTOK * 512];
__device__ unsigned g_wqRH[D3 * 512],   g_wqRL[D3 * 512];
__device__ unsigned g_wqIH[D3 * 512],   g_wqIL[D3 * 512];
__device__ unsigned g_woRH[DMODEL * 512], g_woRL[DMODEL * 512];
__device__ unsigned g_woIH[DMODEL * 512], g_woIL[DMODEL * 512];
__device__ unsigned g_aoRH[NTOK * 512], g_aoRL[NTOK * 512];   // attn out (pre-split)
__device__ unsigned g_aoIH[NTOK * 512], g_aoIL[NTOK * 512];
// rotated K, bf16 H/L packed pairs, layout [bh][s][d-pair word] (B-frag ready)
__device__ unsigned g_kbrH[BH * 512 * 32], g_kbrL[BH * 512 * 32];
__device__ unsigned g_kbiH[BH * 512 * 32], g_kbiL[BH * 512 * 32];
// V transposed, bf16 H/L packed pairs, layout [bh][d][s-pair word] (B-frag ready)
__device__ unsigned g_vtrH[BH * 64 * 256], g_vtrL[BH * 64 * 256];
__device__ unsigned g_vtiH[BH * 64 * 256], g_vtiL[BH * 64 * 256];

// ---------------- RoPE rotor table ----------------
__global__ void rope_table_kernel() {
    int s = blockIdx.x, d = threadIdx.x;
    float inv = powf(10000.0f, -((float)d) / 64.0f);
    float ang = (float)s * inv;
    g_rc[s * DHEAD + d] = cosf(ang);
    g_rs[s * DHEAD + d] = sinf(ang);
}

// ---------------- fp32 -> bf16 H/L pack (float4 per thread) ----------------
__global__ __launch_bounds__(256)
void pack_kernel(const float* __restrict__ src,
                 unsigned* __restrict__ H, unsigned* __restrict__ L)
{
    int i = blockIdx.x * 256 + threadIdx.x;   // word-pair index
    float4 v = ((const float4*)src)[i];
    uint2 h, l;
    split_pair(v.x, v.y, h.x, l.x);
    split_pair(v.z, v.w, h.y, l.y);
    ((uint2*)H)[i] = h;
    ((uint2*)L)[i] = l;
}

// ======= complex GEMM, pre-split bf16 H/L inputs: C = A * B^T =======
// R9-proven structure: tile 64x64x16, 128 threads (4 warps 2x2), stride-12 smem.
// Load phase is now a pure uint4 copy (no conversion); Bi negation via reg XOR.
#define SSTW 12
__global__ __launch_bounds__(128)
void cgemm_pk_kernel(const unsigned* __restrict__ aRH, const unsigned* __restrict__ aRL,
                     const unsigned* __restrict__ aIH, const unsigned* __restrict__ aIL,
                     const unsigned* __restrict__ bRH, const unsigned* __restrict__ bRL,
                     const unsigned* __restrict__ bIH, const unsigned* __restrict__ bIL,
                     float* __restrict__ Cr, float* __restrict__ Ci,
                     int N, int Kw /* K/2 words per row */)
{
    __shared__ unsigned sRH[64 * SSTW], sRL[64 * SSTW];
    __shared__ unsigned sIH[64 * SSTW], sIL[64 * SSTW];
    __shared__ unsigned tRH[64 * SSTW], tRL[64 * SSTW];
    __shared__ unsigned tIH[64 * SSTW], tIL[64 * SSTW];

    int tid  = threadIdx.x;
    int lane = tid & 31, warp = tid >> 5;
    int wm = (warp & 1) * 32;
    int wn = (warp >> 1) * 32;
    int g = lane >> 2, t = lane & 3;
    int m0 = blockIdx.y * 64;
    int n0 = blockIdx.x * 64;

    int lrow = tid >> 1;
    int half = tid & 1;
    int so = lrow * SSTW + half * 4;
    size_t srcA = (size_t)(m0 + lrow) * Kw + half * 4;
    size_t srcB = (size_t)(n0 + lrow) * Kw + half * 4;

    float accR[8][4], accI[8][4];
#pragma unroll
    for (int p = 0; p < 8; p++)
#pragma unroll
        for (int j = 0; j < 4; j++) { accR[p][j] = 0.f; accI[p][j] = 0.f; }

    int NK = Kw / 8;
    for (int kt = 0; kt < NK; kt++) {
        size_t ko = (size_t)kt * 8;
        // global loads issued early (overlap previous tile's MMA phase)
        uint4 vaRH = *(const uint4*)(aRH + srcA + ko);
        uint4 vaRL = *(const uint4*)(aRL + srcA + ko);
        uint4 vaIH = *(const uint4*)(aIH + srcA + ko);
        uint4 vaIL = *(const uint4*)(aIL + srcA + ko);
        uint4 vbRH = *(const uint4*)(bRH + srcB + ko);
        uint4 vbRL = *(const uint4*)(bRL + srcB + ko);
        uint4 vbIH = *(const uint4*)(bIH + srcB + ko);
        uint4 vbIL = *(const uint4*)(bIL + srcB + ko);

        __syncthreads();   // previous iter's frag reads done

        *(uint4*)(sRH + so) = vaRH;  *(uint4*)(sRL + so) = vaRL;
        *(uint4*)(sIH + so) = vaIH;  *(uint4*)(sIL + so) = vaIL;
        *(uint4*)(tRH + so) = vbRH;  *(uint4*)(tRL + so) = vbRL;
        *(uint4*)(tIH + so) = vbIH;  *(uint4*)(tIL + so) = vbIL;

        __syncthreads();

        // A fragments (stride 12, conflict-free, verified since R7)
        unsigned fRH[2][4], fRL[2][4], fIH[2][4], fIL[2][4];
#pragma unroll
        for (int mt = 0; mt < 2; mt++) {
            int r0 = (wm + mt * 16 + g) * SSTW + t;
            int r1 = r0 + 8 * SSTW;
            fRH[mt][0] = sRH[r0]; fRH[mt][1] = sRH[r1];
            fRH[mt][2] = sRH[r0 + 4]; fRH[mt][3] = sRH[r1 + 4];
            fRL[mt][0] = sRL[r0]; fRL[mt][1] = sRL[r1];
            fRL[mt][2] = sRL[r0 + 4]; fRL[mt][3] = sRL[r1 + 4];
            fIH[mt][0] = sIH[r0]; fIH[mt][1] = sIH[r1];
            fIH[mt][2] = sIH[r0 + 4]; fIH[mt][3] = sIH[r1 + 4];
            fIL[mt][0] = sIL[r0]; fIL[mt][1] = sIL[r1];
            fIL[mt][2] = sIL[r0 + 4]; fIL[mt][3] = sIL[r1 + 4];
        }

#pragma unroll
        for (int nt = 0; nt < 4; nt++) {
            int rb = (wn + nt * 8 + g) * SSTW + t;
            unsigned brH[2] = {tRH[rb], tRH[rb + 4]};
            unsigned brL[2] = {tRL[rb], tRL[rb + 4]};
            unsigned biH[2] = {tIH[rb], tIH[rb + 4]};
            unsigned biL[2] = {tIL[rb], tIL[rb + 4]};
            unsigned nbiH[2] = {biH[0] ^ 0x80008000u, biH[1] ^ 0x80008000u};
            unsigned nbiL[2] = {biL[0] ^ 0x80008000u, biL[1] ^ 0x80008000u};
#pragma unroll
            for (int mt = 0; mt < 2; mt++) {
                int p = mt * 4 + nt;
                // re = Ar*Br - Ai*Bi   (3-term compensated each)
                mma_bf16(accR[p], fRH[mt], brH);
                mma_bf16(accR[p], fRH[mt], brL);
                mma_bf16(accR[p], fRL[mt], brH);
                mma_bf16(accR[p], fIH[mt], nbiH);
                mma_bf16(accR[p], fIH[mt], nbiL);
                mma_bf16(accR[p], fIL[mt], nbiH);
                // im = Ar*Bi + Ai*Br
                mma_bf16(accI[p], fRH[mt], biH);
                mma_bf16(accI[p], fRH[mt], biL);
                mma_bf16(accI[p], fRL[mt], biH);
                mma_bf16(accI[p], fIH[mt], brH);
                mma_bf16(accI[p], fIH[mt], brL);
                mma_bf16(accI[p], fIL[mt], brH);
            }
        }
    }

    // epilogue
#pragma unroll
    for (int mt = 0; mt < 2; mt++)
#pragma unroll
        for (int nt = 0; nt < 4; nt++) {
            int p = mt * 4 + nt;
            int m = m0 + wm + mt * 16 + g;
            int n = n0 + wn + nt * 8 + t * 2;
            size_t c0 = (size_t)m * N + n;
            size_t c1 = (size_t)(m + 8) * N + n;
            *(float2*)(Cr + c0) = make_float2(accR[p][0], accR[p][1]);
            *(float2*)(Cr + c1) = make_float2(accR[p][2], accR[p][3]);
            *(float2*)(Ci + c0) = make_float2(accI[p][0], accI[p][1]);
            *(float2*)(Ci + c1) = make_float2(accI[p][2], accI[p][3]);
        }
}

// ---------- K: rotate + split to bf16 H/L pairs, layout [bh][s][d-pair] ----------
__global__ __launch_bounds__(256)
void kpack_kernel(const float* __restrict__ qkv_r, const float* __restrict__ qkv_i)
{
    int bh = blockIdx.y;
    int b = bh >> 4, h = bh & 15;
    int id = blockIdx.x * 256 + threadIdx.x;   // 0..16383 = s*32 + wd
    int s = id >> 5, wd = id & 31;
    int d = 2 * wd;
    size_t off = ((size_t)b * S_LEN + s) * D3 + DMODEL + (size_t)h * DHEAD + d;
    float2 kr = *(const float2*)(qkv_r + off);
    float2 ki = *(const float2*)(qkv_i + off);
    float2 co = *(const float2*)(g_rc + s * DHEAD + d);
    float2 si = *(const float2*)(g_rs + s * DHEAD + d);
    float r0 = kr.x * co.x - ki.x * si.x;
    float i0 = kr.x * si.x + ki.x * co.x;
    float r1 = kr.y * co.y - ki.y * si.y;
    float i1 = kr.y * si.y + ki.y * co.y;
    size_t o = (size_t)bh * 16384 + id;
    unsigned H, L;
    split_pair(r0, r1, H, L); g_kbrH[o] = H; g_kbrL[o] = L;
    split_pair(i0, i1, H, L); g_kbiH[o] = H; g_kbiL[o] = L;
}

// ---------- V: transpose + split to bf16 H/L pairs, layout [bh][d][s-pair] ----------
__global__ __launch_bounds__(256)
void vpack_kernel(const float* __restrict__ qkv_r, const float* __restrict__ qkv_i)
{
    __shared__ float sVr[64][65], sVi[64][65];
    int sc = blockIdx.x;       // s-chunk of 64
    int bh = blockIdx.y;
    int b = bh >> 4, h = bh & 15;
    int tid = threadIdx.x;

#pragma unroll
    for (int i = 0; i < 16; i++) {
        int id = i * 256 + tid;        // 0..4095 = sl*64 + d
        int sl = id >> 6, d = id & 63;
        size_t off = ((size_t)b * S_LEN + sc * 64 + sl) * D3 + 2 * DMODEL
                   + (size_t)h * DHEAD + d;
        sVr[sl][d] = qkv_r[off];
        sVi[sl][d] = qkv_i[off];
    }
    __syncthreads();

#pragma unroll
    for (int i = 0; i < 8; i++) {
        int id = i * 256 + tid;        // 0..2047 = d*32 + ws
        int d = id >> 5, ws = id & 31;
        size_t o = ((size_t)bh * 64 + d) * 256 + sc * 32 + ws;
        unsigned H, L;
        split_pair(sVr[2 * ws][d], sVr[2 * ws + 1][d], H, L);
        g_vtrH[o] = H; g_vtrL[o] = L;
        split_pair(sVi[2 * ws][d], sVi[2 * ws + 1][d], H, L);
        g_vtiH[o] = H; g_vtiL[o] = L;
    }
}

// ========== fused attention, all-MMA: one block per (b, h, 16-q tile) ==========
#define OFF_QRH 0
#define OFF_QRL 576
#define OFF_QIH 1152
#define OFF_QIL 1728
#define OFF_WC  2304
#define OFF_WS  10528
#define OFF_WCH 18752
#define OFF_WCL 22912
#define OFF_WSH 27072
#define OFF_WSL 31232
#define ATTN_SMEM_WORDS 35392
#define ATTN_SMEM (ATTN_SMEM_WORDS * 4)

__global__ __launch_bounds__(256)
void attn_kernel(const float* __restrict__ qkv_r, const float* __restrict__ qkv_i)
{
    extern __shared__ unsigned sm[];
    unsigned* sQrH = sm + OFF_QRH;
    unsigned* sQrL = sm + OFF_QRL;
    unsigned* sQiH = sm + OFF_QIH;
    unsigned* sQiL = sm + OFF_QIL;
    float* sWc = (float*)(sm + OFF_WC);
    float* sWs = (float*)(sm + OFF_WS);
    unsigned* sWcH = sm + OFF_WCH;
    unsigned* sWcL = sm + OFF_WCL;
    unsigned* sWsH = sm + OFF_WSH;
    unsigned* sWsL = sm + OFF_WSL;

    int tid = threadIdx.x;
    int w = tid >> 5, l = tid & 31;
    int g = l >> 2, t = l & 3;
    int h = blockIdx.y, b = blockIdx.z;
    int bh = b * NHEAD + h;
    int q0 = blockIdx.x * 16;
    const size_t tok = (size_t)b * S_LEN;

    // ---- Q: load + rotate + split, word layout [q][d-pair] stride 36 ----
#pragma unroll
    for (int i = 0; i < 2; i++) {
        int id = tid + 256 * i;        // 0..511 = q*32 + wd
        int q = id >> 5, wd = id & 31;
        int s = q0 + q;
        int d = 2 * wd;
        size_t off = (tok + s) * D3 + (size_t)h * DHEAD + d;
        float2 qr = *(const float2*)(qkv_r + off);
        float2 qi = *(const float2*)(qkv_i + off);
        float2 co = *(const float2*)(g_rc + s * DHEAD + d);
        float2 si = *(const float2*)(g_rs + s * DHEAD + d);
        float r0 = qr.x * co.x - qi.x * si.x;
        float i0 = qr.x * si.x + qi.x * co.x;
        float r1 = qr.y * co.y - qi.y * si.y;
        float i1 = qr.y * si.y + qi.y * co.y;
        unsigned H, L;
        split_pair(r0, r1, H, L); sQrH[q * 36 + wd] = H; sQrL[q * 36 + wd] = L;
        split_pair(i0, i1, H, L); sQiH[q * 36 + wd] = H; sQiL[q * 36 + wd] = L;
    }
    __syncthreads();

    // ---- scores MMA: warp w owns k-rows [64w, 64w+64) ----
    {
        float accR[8][4], accI[8][4];
#pragma unroll
        for (int p = 0; p < 8; p++)
#pragma unroll
            for (int j = 0; j < 4; j++) { accR[p][j] = 0.f; accI[p][j] = 0.f; }

        const size_t kbase = (size_t)bh * 16384;
#pragma unroll
        for (int ks = 0; ks < 4; ks++) {
            int r0 = g * 36 + ks * 8 + t;
            int r1 = (g + 8) * 36 + ks * 8 + t;
            unsigned aQrH[4] = {sQrH[r0], sQrH[r1], sQrH[r0 + 4], sQrH[r1 + 4]};
            unsigned aQrL[4] = {sQrL[r0], sQrL[r1], sQrL[r0 + 4], sQrL[r1 + 4]};
            unsigned aQiH[4] = {sQiH[r0], sQiH[r1], sQiH[r0 + 4], sQiH[r1 + 4]};
            unsigned aQiL[4] = {sQiL[r0], sQiL[r1], sQiL[r0 + 4], sQiL[r1 + 4]};
            unsigned nQrH[4], nQrL[4];
#pragma unroll
            for (int j = 0; j < 4; j++) {
                nQrH[j] = aQrH[j] ^ 0x80008000u;
                nQrL[j] = aQrL[j] ^ 0x80008000u;
            }
#pragma unroll
            for (int nt = 0; nt < 8; nt++) {
                int srow = w * 64 + nt * 8 + g;
                size_t kb = kbase + (size_t)srow * 32 + ks * 8 + t;
                unsigned krH[2] = {g_kbrH[kb], g_kbrH[kb + 4]};
                unsigned krL[2] = {g_kbrL[kb], g_kbrL[kb + 4]};
                unsigned kiH[2] = {g_kbiH[kb], g_kbiH[kb + 4]};
                unsigned kiL[2] = {g_kbiL[kb], g_kbiL[kb + 4]};
                mma_bf16(accR[nt], aQrH, krH);
                mma_bf16(accR[nt], aQrH, krL);
                mma_bf16(accR[nt], aQrL, krH);
                mma_bf16(accR[nt], aQiH, kiH);
                mma_bf16(accR[nt], aQiH, kiL);
                mma_bf16(accR[nt], aQiL, kiH);
                mma_bf16(accI[nt], aQiH, krH);
                mma_bf16(accI[nt], aQiH, krL);
                mma_bf16(accI[nt], aQiL, krH);
                mma_bf16(accI[nt], nQrH, kiH);
                mma_bf16(accI[nt], nQrH, kiL);
                mma_bf16(accI[nt], nQrL, kiH);
            }
        }

        const float scale = 0.125f;   // 1/sqrt(64)
#pragma unroll
        for (int nt = 0; nt < 8; nt++) {
            int col = w * 64 + nt * 8 + 2 * t;
            *(float2*)&sWc[g * 514 + col] =
                make_float2(accR[nt][0] * scale, accR[nt][1] * scale);
            *(float2*)&sWc[(g + 8) * 514 + col] =
                make_float2(accR[nt][2] * scale, accR[nt][3] * scale);
            *(float2*)&sWs[g * 514 + col] =
                make_float2(accI[nt][0] * scale, accI[nt][1] * scale);
            *(float2*)&sWs[(g + 8) * 514 + col] =
                make_float2(accI[nt][2] * scale, accI[nt][3] * scale);
        }
    }
    __syncthreads();

    // ---- softmax + complex weights (bf16 H/L split): warp w -> rows w, w+8 ----
#pragma unroll
    for (int rr = 0; rr < 2; rr++) {
        int row = w + rr * 8;
        float* rc_ = sWc + row * 514;
        float* rs_ = sWs + row * 514;

        float mx = -1e30f;
#pragma unroll
        for (int j = 0; j < 16; j++) mx = fmaxf(mx, rc_[l + 32 * j]);
#pragma unroll
        for (int o = 16; o > 0; o >>= 1)
            mx = fmaxf(mx, __shfl_xor_sync(0xffffffff, mx, o));

        float sum = 0.f;
#pragma unroll
        for (int j = 0; j < 16; j++) {
            int idx = l + 32 * j;
            float e = __expf(rc_[idx] - mx);
            rc_[idx] = e;
            sum += e;
        }
#pragma unroll
        for (int o = 16; o > 0; o >>= 1)
            sum += __shfl_xor_sync(0xffffffff, sum, o);
        float inv = 1.0f / sum;

#pragma unroll
        for (int j = 0; j < 8; j++) {
            int k0 = 2 * l + 64 * j;
            int wd = l + 32 * j;
            float p0 = rc_[k0] * inv, p1 = rc_[k0 + 1] * inv;
            float s0, c0, s1, c1;
            sincosf(rs_[k0], &s0, &c0);
            sincosf(rs_[k0 + 1], &s1, &c1);
            unsigned H, L;
            split_pair(p0 * c0, p1 * c1, H, L);
            sWcH[row * 260 + wd] = H; sWcL[row * 260 + wd] = L;
            split_pair(p0 * s0, p1 * s1, H, L);
            sWsH[row * 260 + wd] = H; sWsL[row * 260 + wd] = L;
        }
    }
    __syncthreads();

    // ---- AV MMA: warp w -> d-cols [8w, 8w+8); epilogue writes pre-split H/L ----
    {
        float oR[4] = {0.f, 0.f, 0.f, 0.f};
        float oI[4] = {0.f, 0.f, 0.f, 0.f};
        const size_t vbase = ((size_t)bh * 64 + 8 * w + g) * 256;
#pragma unroll 4
        for (int ks = 0; ks < 32; ks++) {
            int r0 = g * 260 + ks * 8 + t;
            int r1 = (g + 8) * 260 + ks * 8 + t;
            unsigned awcH[4] = {sWcH[r0], sWcH[r1], sWcH[r0 + 4], sWcH[r1 + 4]};
            unsigned awcL[4] = {sWcL[r0], sWcL[r1], sWcL[r0 + 4], sWcL[r1 + 4]};
            unsigned awsH[4] = {sWsH[r0], sWsH[r1], sWsH[r0 + 4], sWsH[r1 + 4]};
            unsigned awsL[4] = {sWsL[r0], sWsL[r1], sWsL[r0 + 4], sWsL[r1 + 4]};
            unsigned nwsH[4], nwsL[4];
#pragma unroll
            for (int j = 0; j < 4; j++) {
                nwsH[j] = awsH[j] ^ 0x80008000u;
                nwsL[j] = awsL[j] ^ 0x80008000u;
            }
            size_t vb = vbase + ks * 8 + t;
            unsigned vrH[2] = {g_vtrH[vb], g_vtrH[vb + 4]};
            unsigned vrL[2] = {g_vtrL[vb], g_vtrL[vb + 4]};
            unsigned viH[2] = {g_vtiH[vb], g_vtiH[vb + 4]};
            unsigned viL[2] = {g_vtiL[vb], g_vtiL[vb + 4]};
            mma_bf16(oR, awcH, vrH);
            mma_bf16(oR, awcH, vrL);
            mma_bf16(oR, awcL, vrH);
            mma_bf16(oR, nwsH, viH);
            mma_bf16(oR, nwsH, viL);
            mma_bf16(oR, nwsL, viH);
            mma_bf16(oI, awcH, viH);
            mma_bf16(oI, awcH, viL);
            mma_bf16(oI, awcL, viH);
            mma_bf16(oI, awsH, vrH);
            mma_bf16(oI, awsH, vrL);
            mma_bf16(oI, awsL, vrH);
        }
        int wcol = h * 32 + 4 * w + t;          // word col in [tok][512] layout
        size_t r0w = (tok + q0 + g) * 512 + wcol;
        size_t r1w = (tok + q0 + g + 8) * 512 + wcol;
        unsigned H, L;
        split_pair(oR[0], oR[1], H, L); g_aoRH[r0w] = H; g_aoRL[r0w] = L;
        split_pair(oR[2], oR[3], H, L); g_aoRH[r1w] = H; g_aoRL[r1w] = L;
        split_pair(oI[0], oI[1], H, L); g_aoIH[r0w] = H; g_aoIL[r0w] = L;
        split_pair(oI[2], oI[3], H, L); g_aoIH[r1w] = H; g_aoIL[r1w] = L;
    }
}

// ---------------- launch ----------------
extern "C" void kernel_launch(void* const* d_in, const int* in_sizes, int n_in,
                              void* d_out, int out_size)
{
    const float* x_re    = (const float*)d_in[0];
    const float* x_im    = (const float*)d_in[1];
    const float* wqkv_re = (const float*)d_in[2];
    const float* wqkv_im = (const float*)d_in[3];
    const float* wo_re   = (const float*)d_in[4];
    const float* wo_im   = (const float*)d_in[5];
    float* out = (float*)d_out;

    float *qkv_r, *qkv_i;
    cudaGetSymbolAddress((void**)&qkv_r, g_qkv_r);
    cudaGetSymbolAddress((void**)&qkv_i, g_qkv_i);
    unsigned *xRH, *xRL, *xIH, *xIL, *wqRH, *wqRL, *wqIH, *wqIL;
    unsigned *woRH, *woRL, *woIH, *woIL, *aoRH, *aoRL, *aoIH, *aoIL;
    cudaGetSymbolAddress((void**)&xRH, g_xRH);   cudaGetSymbolAddress((void**)&xRL, g_xRL);
    cudaGetSymbolAddress((void**)&xIH, g_xIH);   cudaGetSymbolAddress((void**)&xIL, g_xIL);
    cudaGetSymbolAddress((void**)&wqRH, g_wqRH); cudaGetSymbolAddress((void**)&wqRL, g_wqRL);
    cudaGetSymbolAddress((void**)&wqIH, g_wqIH); cudaGetSymbolAddress((void**)&wqIL, g_wqIL);
    cudaGetSymbolAddress((void**)&woRH, g_woRH); cudaGetSymbolAddress((void**)&woRL, g_woRL);
    cudaGetSymbolAddress((void**)&woIH, g_woIH); cudaGetSymbolAddress((void**)&woIL, g_woIL);
    cudaGetSymbolAddress((void**)&aoRH, g_aoRH); cudaGetSymbolAddress((void**)&aoRL, g_aoRL);
    cudaGetSymbolAddress((void**)&aoIH, g_aoIH); cudaGetSymbolAddress((void**)&aoIL, g_aoIL);

    cudaFuncSetAttribute(attn_kernel,
                         cudaFuncAttributeMaxDynamicSharedMemorySize, ATTN_SMEM);

    // 1. RoPE rotor table + operand pre-splits (float4-vectorized)
    rope_table_kernel<<<S_LEN, DHEAD>>>();
    pack_kernel<<<NTOK * 256 / 256, 256>>>(x_re, xRH, xRL);
    pack_kernel<<<NTOK * 256 / 256, 256>>>(x_im, xIH, xIL);
    pack_kernel<<<D3 * 256 / 256, 256>>>(wqkv_re, wqRH, wqRL);
    pack_kernel<<<D3 * 256 / 256, 256>>>(wqkv_im, wqIH, wqIL);
    pack_kernel<<<DMODEL * 256 / 256, 256>>>(wo_re, woRH, woRL);
    pack_kernel<<<DMODEL * 256 / 256, 256>>>(wo_im, woIH, woIL);

    // 2. complex QKV projection (R9 structure, pre-split inputs)
    dim3 g1(D3 / 64, NTOK / 64);
    cgemm_pk_kernel<<<g1, 128>>>(xRH, xRL, xIH, xIL,
                                 wqRH, wqRL, wqIH, wqIL,
                                 qkv_r, qkv_i, D3, DMODEL / 2);

    // 3. K rotate+split and V transpose+split into MMA-ready bf16 H/L arrays
    dim3 g2(64, BH);
    kpack_kernel<<<g2, 256>>>(qkv_r, qkv_i);
    dim3 g3(S_LEN / 64, BH);
    vpack_kernel<<<g3, 256>>>(qkv_r, qkv_i);

    // 4. fused all-MMA attention, 16 q-rows per block (writes pre-split output)
    dim3 g4(S_LEN / 16, NHEAD, BATCH);
    attn_kernel<<<g4, 256, ATTN_SMEM>>>(qkv_r, qkv_i);

    // 5. complex output projection straight into d_out ([2,B,S,D])
    dim3 g5(DMODEL / 64, NTOK / 64);
    cgemm_pk_kernel<<<g5, 128>>>(aoRH, aoRL, aoIH, aoIL,
                                 woRH, woRL, woIH, woIL,
                                 out, out + (size_t)NTOK * DMODEL,
                                 DMODEL, DMODEL / 2);
}